// round 3
// baseline (speedup 1.0000x reference)
#include <cuda_runtime.h>
#include <math_constants.h>

// Problem constants (fixed shapes from setup_inputs)
#define BB 8
#define LP1 25
#define LL 24
#define TT 512
#define DD 1024
#define PP 128
#define TOPK 3

#define SPLIT1 4    // T-splits for score pass  -> 8*24*4 = 768 blocks
#define SPLIT3 64   // T-splits for gather pass -> 8*64   = 512 blocks

// Output layout: flattened tuple in reference order, all fp32
//   projected       : BB*PP          = 1024   @ 0
//   scores          : BB*LL          = 192    @ 1024
//   topk_idx (float): BB*TOPK        = 24     @ 1216
//   selected_layers : BB*TOPK*TT*DD  = 12582912 @ 1240
#define OFF_PROJ   0
#define OFF_SCORES 1024
#define OFF_IDX    1216
#define OFF_SEL    1240

// Scratch (device globals; allocation-free)
__device__ float g_score_partial[BB * LL * SPLIT1];
__device__ int   g_topk_idx[BB * TOPK];
__device__ float g_topk_val[BB * TOPK];
__device__ float g_pooled[BB * DD];      // atomic-max accumulator (32 KB, L2-resident)

// Exact, order-independent float atomic max (bit trick).
__device__ __forceinline__ void atomicMaxFloat(float* addr, float v) {
    if (v >= 0.0f) {
        atomicMax((int*)addr, __float_as_int(v));
    } else {
        atomicMin((unsigned int*)addr, __float_as_uint(v));
    }
}

// ---------------------------------------------------------------------------
// Kernel 1: per-(b,l) score partials.
// score(b,l) = (1/T) * sum_{t,d} x[b,l+1,t,d] * w_score[d]
// 256 threads: each thread owns a fixed float4 of the D dimension.
// ---------------------------------------------------------------------------
__global__ __launch_bounds__(256) void k_scores(const float* __restrict__ x,
                                                const float* __restrict__ w_score) {
    const int blk = blockIdx.x;           // 0 .. BB*LL*SPLIT1-1
    const int s   = blk % SPLIT1;
    const int bl  = blk / SPLIT1;
    const int l   = bl % LL;
    const int b   = bl / LL;
    const int tid = threadIdx.x;

    const float4* __restrict__ base =
        (const float4*)(x + ((size_t)b * LP1 + (size_t)(l + 1)) * TT * DD);
    const float4 w4 = ((const float4*)w_score)[tid];

    float acc = 0.f;
    const int t0 = s * (TT / SPLIT1);
    #pragma unroll 8
    for (int t = t0; t < t0 + TT / SPLIT1; ++t) {
        float4 v = base[(size_t)t * (DD / 4) + tid];
        acc += v.x * w4.x + v.y * w4.y + v.z * w4.z + v.w * w4.w;
    }

    __shared__ float sm[256];
    sm[tid] = acc;
    __syncthreads();
    #pragma unroll
    for (int st = 128; st > 0; st >>= 1) {
        if (tid < st) sm[tid] += sm[tid + st];
        __syncthreads();
    }
    if (tid == 0) g_score_partial[bl * SPLIT1 + s] = sm[0];
}

// ---------------------------------------------------------------------------
// Kernel 2: finish scores, softmax over L, top-3 (desc, low-index tie-break).
// Also re-initializes g_pooled to -inf for the gather pass (every launch).
// One block. Writes scores + topk_idx(as float) to out, idx/val to scratch.
// ---------------------------------------------------------------------------
__global__ __launch_bounds__(256) void k_topk(const float* __restrict__ b_score,
                                              float* __restrict__ out) {
    __shared__ float sc[BB * LL];
    const int tid = threadIdx.x;

    // init atomic-max accumulator
    #pragma unroll
    for (int i = tid; i < BB * DD; i += 256) g_pooled[i] = -CUDART_INF_F;

    if (tid < BB * LL) {
        float s = 0.f;
        #pragma unroll
        for (int i = 0; i < SPLIT1; ++i) s += g_score_partial[tid * SPLIT1 + i];
        s = s * (1.0f / (float)TT) + b_score[0];
        sc[tid] = s;
        out[OFF_SCORES + tid] = s;
    }
    __syncthreads();

    if (tid < BB) {
        const int b = tid;
        float m = -CUDART_INF_F;
        #pragma unroll
        for (int l = 0; l < LL; ++l) m = fmaxf(m, sc[b * LL + l]);
        float p[LL];
        float sum = 0.f;
        #pragma unroll
        for (int l = 0; l < LL; ++l) { p[l] = expf(sc[b * LL + l] - m); sum += p[l]; }
        const float inv = 1.0f / sum;
        #pragma unroll
        for (int l = 0; l < LL; ++l) p[l] *= inv;

        bool used[LL];
        #pragma unroll
        for (int l = 0; l < LL; ++l) used[l] = false;

        for (int k = 0; k < TOPK; ++k) {
            int   best = 0;
            float bv   = -CUDART_INF_F;
            #pragma unroll
            for (int l = 0; l < LL; ++l) {
                if (!used[l] && p[l] > bv) { bv = p[l]; best = l; }
            }
            used[best] = true;
            g_topk_idx[b * TOPK + k] = best;
            g_topk_val[b * TOPK + k] = bv;
            out[OFF_IDX + b * TOPK + k] = (float)best;
        }
    }
}

// ---------------------------------------------------------------------------
// Kernel 3: gather 3 selected layers -> write selected_layers output
// (streaming stores), fused weighted sum + block-local max over T, then
// exact atomic max into g_pooled.
// Grid: BB*SPLIT3 blocks, 256 threads, each thread owns a fixed float4 of D.
// ---------------------------------------------------------------------------
__global__ __launch_bounds__(256) void k_gather(const float* __restrict__ x,
                                                float* __restrict__ out) {
    const int blk = blockIdx.x;             // 0 .. BB*SPLIT3-1
    const int s   = blk % SPLIT3;
    const int b   = blk / SPLIT3;
    const int tid = threadIdx.x;

    const int i0 = g_topk_idx[b * TOPK + 0];
    const int i1 = g_topk_idx[b * TOPK + 1];
    const int i2 = g_topk_idx[b * TOPK + 2];
    const float v0 = g_topk_val[b * TOPK + 0];
    const float v1 = g_topk_val[b * TOPK + 1];
    const float v2 = g_topk_val[b * TOPK + 2];

    const float4* __restrict__ p0 =
        (const float4*)(x + ((size_t)b * LP1 + (size_t)(i0 + 1)) * TT * DD);
    const float4* __restrict__ p1 =
        (const float4*)(x + ((size_t)b * LP1 + (size_t)(i1 + 1)) * TT * DD);
    const float4* __restrict__ p2 =
        (const float4*)(x + ((size_t)b * LP1 + (size_t)(i2 + 1)) * TT * DD);

    float* __restrict__ sel = out + OFF_SEL;
    float4* __restrict__ o0 = (float4*)(sel + ((size_t)b * TOPK + 0) * TT * DD);
    float4* __restrict__ o1 = (float4*)(sel + ((size_t)b * TOPK + 1) * TT * DD);
    float4* __restrict__ o2 = (float4*)(sel + ((size_t)b * TOPK + 2) * TT * DD);

    const int TPS = TT / SPLIT3;   // 8 rows per block
    float4 mx = make_float4(-CUDART_INF_F, -CUDART_INF_F, -CUDART_INF_F, -CUDART_INF_F);

    #pragma unroll
    for (int tt = 0; tt < TPS; ++tt) {
        const size_t off = (size_t)(s * TPS + tt) * (DD / 4) + tid;
        float4 a = p0[off];
        float4 c = p1[off];
        float4 e = p2[off];
        // streaming stores: selected_layers is write-once, never re-read
        __stcs(&o0[off], a);
        __stcs(&o1[off], c);
        __stcs(&o2[off], e);
        float4 w;
        w.x = v0 * a.x + v1 * c.x + v2 * e.x;
        w.y = v0 * a.y + v1 * c.y + v2 * e.y;
        w.z = v0 * a.z + v1 * c.z + v2 * e.z;
        w.w = v0 * a.w + v1 * c.w + v2 * e.w;
        mx.x = fmaxf(mx.x, w.x);
        mx.y = fmaxf(mx.y, w.y);
        mx.z = fmaxf(mx.z, w.z);
        mx.w = fmaxf(mx.w, w.w);
    }

    float* gp = g_pooled + (size_t)b * DD + tid * 4;
    atomicMaxFloat(gp + 0, mx.x);
    atomicMaxFloat(gp + 1, mx.y);
    atomicMaxFloat(gp + 2, mx.z);
    atomicMaxFloat(gp + 3, mx.w);
}

// ---------------------------------------------------------------------------
// Kernel 4: read pooled max (1 load/thread), LayerNorm, project 1024->128.
// 1024 threads/block, grid=BB.
// ---------------------------------------------------------------------------
__global__ __launch_bounds__(1024) void k_final(const float* __restrict__ gamma,
                                                const float* __restrict__ beta,
                                                const float* __restrict__ w_proj,
                                                const float* __restrict__ b_proj,
                                                float* __restrict__ out) {
    const int b   = blockIdx.x;
    const int tid = threadIdx.x;          // 0..1023 ; owns dim d = tid

    __shared__ float pooled[DD];          // normed values after Phase B
    __shared__ float red[32];
    __shared__ float red2[32];
    __shared__ float partial[1024];       // [chunk][p] projection partials
    __shared__ float s_stats[2];          // mu, rstd

    // --- Phase A: single coalesced load of the pooled max ---
    const float m = g_pooled[(size_t)b * DD + tid];

    // --- Phase B: LN stats (sum, sumsq) over 1024 values ---
    {
        float s1 = m, s2 = m * m;
        #pragma unroll
        for (int o = 16; o > 0; o >>= 1) {
            s1 += __shfl_down_sync(0xffffffffu, s1, o);
            s2 += __shfl_down_sync(0xffffffffu, s2, o);
        }
        const int lane = tid & 31, warp = tid >> 5;
        if (lane == 0) { red[warp] = s1; red2[warp] = s2; }
    }
    __syncthreads();
    if (tid < 32) {
        float s1 = red[tid], s2 = red2[tid];
        #pragma unroll
        for (int o = 16; o > 0; o >>= 1) {
            s1 += __shfl_down_sync(0xffffffffu, s1, o);
            s2 += __shfl_down_sync(0xffffffffu, s2, o);
        }
        if (tid == 0) {
            float mu  = s1 * (1.0f / (float)DD);
            float var = s2 * (1.0f / (float)DD) - mu * mu;
            s_stats[0] = mu;
            s_stats[1] = rsqrtf(var + 1e-5f);
        }
    }
    __syncthreads();

    // normalize
    {
        const float mu = s_stats[0], rstd = s_stats[1];
        pooled[tid] = (m - mu) * rstd * gamma[tid] + beta[tid];
    }
    __syncthreads();

    // --- Phase C: projection. chunk = tid>>7 (0..7), p = tid&127 ---
    {
        const int p     = tid & (PP - 1);
        const int chunk = tid >> 7;
        const int d0    = chunk * 128;
        float acc = 0.f;
        #pragma unroll 8
        for (int i = 0; i < 128; ++i) {
            const int d = d0 + i;
            acc += pooled[d] * w_proj[(size_t)d * PP + p];
        }
        partial[chunk * PP + p] = acc;
    }
    __syncthreads();
    if (tid < PP) {
        float acc = b_proj[tid];
        #pragma unroll
        for (int c = 0; c < 8; ++c) acc += partial[c * PP + tid];
        out[OFF_PROJ + b * PP + tid] = acc;
    }
}

// ---------------------------------------------------------------------------
// Launch
// ---------------------------------------------------------------------------
extern "C" void kernel_launch(void* const* d_in, const int* in_sizes, int n_in,
                              void* d_out, int out_size) {
    const float* x       = (const float*)d_in[0];  // wav2vec_ft (8,25,512,1024)
    const float* w_score = (const float*)d_in[1];  // (1024,1)
    const float* b_score = (const float*)d_in[2];  // (1,)
    const float* ln_g    = (const float*)d_in[3];  // (1024,)
    const float* ln_b    = (const float*)d_in[4];  // (1024,)
    const float* w_proj  = (const float*)d_in[5];  // (1024,128)
    const float* b_proj  = (const float*)d_in[6];  // (128,)
    float* out = (float*)d_out;

    k_scores<<<BB * LL * SPLIT1, 256>>>(x, w_score);
    k_topk<<<1, 256>>>(b_score, out);
    k_gather<<<BB * SPLIT3, 256>>>(x, out);
    k_final<<<BB, 1024>>>(ln_g, ln_b, w_proj, b_proj, out);
}

// round 4
// speedup vs baseline: 1.0206x; 1.0206x over previous
#include <cuda_runtime.h>
#include <math_constants.h>

// Problem constants (fixed shapes from setup_inputs)
#define BB 8
#define LP1 25
#define LL 24
#define TT 512
#define DD 1024
#define PP 128
#define TOPK 3

#define SPLIT1 4    // T-splits for score pass  -> 8*24*4 = 768 blocks
#define SPLIT3 64   // T-splits for gather pass -> 8*64   = 512 blocks
#define FBLK   4    // p-slices per batch in k_final -> 32 blocks

// Output layout: flattened tuple in reference order, all fp32
//   projected       : BB*PP          = 1024   @ 0
//   scores          : BB*LL          = 192    @ 1024
//   topk_idx (float): BB*TOPK        = 24     @ 1216
//   selected_layers : BB*TOPK*TT*DD  = 12582912 @ 1240
#define OFF_PROJ   0
#define OFF_SCORES 1024
#define OFF_IDX    1216
#define OFF_SEL    1240

// Scratch (device globals; allocation-free)
__device__ float g_score_partial[BB * LL * SPLIT1];
__device__ int   g_topk_idx[BB * TOPK];
__device__ float g_topk_val[BB * TOPK];
__device__ float g_pooled[BB * DD];      // atomic-max accumulator (32 KB, L2-resident)

// Exact, order-independent float atomic max (bit trick).
__device__ __forceinline__ void atomicMaxFloat(float* addr, float v) {
    if (v >= 0.0f) {
        atomicMax((int*)addr, __float_as_int(v));
    } else {
        atomicMin((unsigned int*)addr, __float_as_uint(v));
    }
}

// ---------------------------------------------------------------------------
// Kernel 1: per-(b,l) score partials; first 32 blocks also init g_pooled.
// score(b,l) = (1/T) * sum_{t,d} x[b,l+1,t,d] * w_score[d]
// ---------------------------------------------------------------------------
__global__ __launch_bounds__(256) void k_scores(const float* __restrict__ x,
                                                const float* __restrict__ w_score) {
    const int blk = blockIdx.x;           // 0 .. BB*LL*SPLIT1-1
    const int tid = threadIdx.x;

    // init atomic-max accumulator for the gather pass (stream-ordered before it)
    if (blk < 32) g_pooled[blk * 256 + tid] = -CUDART_INF_F;

    const int s   = blk % SPLIT1;
    const int bl  = blk / SPLIT1;
    const int l   = bl % LL;
    const int b   = bl / LL;

    const float4* __restrict__ base =
        (const float4*)(x + ((size_t)b * LP1 + (size_t)(l + 1)) * TT * DD);
    const float4 w4 = ((const float4*)w_score)[tid];

    float acc = 0.f;
    const int t0 = s * (TT / SPLIT1);
    #pragma unroll 8
    for (int t = t0; t < t0 + TT / SPLIT1; ++t) {
        float4 v = base[(size_t)t * (DD / 4) + tid];
        acc += v.x * w4.x + v.y * w4.y + v.z * w4.z + v.w * w4.w;
    }

    __shared__ float sm[256];
    sm[tid] = acc;
    __syncthreads();
    #pragma unroll
    for (int st = 128; st > 0; st >>= 1) {
        if (tid < st) sm[tid] += sm[tid + st];
        __syncthreads();
    }
    if (tid == 0) g_score_partial[bl * SPLIT1 + s] = sm[0];
}

// ---------------------------------------------------------------------------
// Kernel 2: finish scores, softmax over L, top-3 (desc, low-index tie-break).
// One block. Writes scores + topk_idx(as float) to out, idx/val to scratch.
// ---------------------------------------------------------------------------
__global__ __launch_bounds__(256) void k_topk(const float* __restrict__ b_score,
                                              float* __restrict__ out) {
    __shared__ float sc[BB * LL];
    const int tid = threadIdx.x;

    if (tid < BB * LL) {
        float s = 0.f;
        #pragma unroll
        for (int i = 0; i < SPLIT1; ++i) s += g_score_partial[tid * SPLIT1 + i];
        s = s * (1.0f / (float)TT) + b_score[0];
        sc[tid] = s;
        out[OFF_SCORES + tid] = s;
    }
    __syncthreads();

    if (tid < BB) {
        const int b = tid;
        float m = -CUDART_INF_F;
        #pragma unroll
        for (int l = 0; l < LL; ++l) m = fmaxf(m, sc[b * LL + l]);
        float p[LL];
        float sum = 0.f;
        #pragma unroll
        for (int l = 0; l < LL; ++l) { p[l] = expf(sc[b * LL + l] - m); sum += p[l]; }
        const float inv = 1.0f / sum;
        #pragma unroll
        for (int l = 0; l < LL; ++l) p[l] *= inv;

        bool used[LL];
        #pragma unroll
        for (int l = 0; l < LL; ++l) used[l] = false;

        for (int k = 0; k < TOPK; ++k) {
            int   best = 0;
            float bv   = -CUDART_INF_F;
            #pragma unroll
            for (int l = 0; l < LL; ++l) {
                if (!used[l] && p[l] > bv) { bv = p[l]; best = l; }
            }
            used[best] = true;
            g_topk_idx[b * TOPK + k] = best;
            g_topk_val[b * TOPK + k] = bv;
            out[OFF_IDX + b * TOPK + k] = (float)best;
        }
    }
}

// ---------------------------------------------------------------------------
// Kernel 3: gather 3 selected layers -> write selected_layers output
// (streaming stores), fused weighted sum + block-local max over T, then
// exact atomic max into g_pooled.
// Grid: BB*SPLIT3 blocks, 256 threads, each thread owns a fixed float4 of D.
// ---------------------------------------------------------------------------
__global__ __launch_bounds__(256) void k_gather(const float* __restrict__ x,
                                                float* __restrict__ out) {
    const int blk = blockIdx.x;             // 0 .. BB*SPLIT3-1
    const int s   = blk % SPLIT3;
    const int b   = blk / SPLIT3;
    const int tid = threadIdx.x;

    const int i0 = g_topk_idx[b * TOPK + 0];
    const int i1 = g_topk_idx[b * TOPK + 1];
    const int i2 = g_topk_idx[b * TOPK + 2];
    const float v0 = g_topk_val[b * TOPK + 0];
    const float v1 = g_topk_val[b * TOPK + 1];
    const float v2 = g_topk_val[b * TOPK + 2];

    const float4* __restrict__ p0 =
        (const float4*)(x + ((size_t)b * LP1 + (size_t)(i0 + 1)) * TT * DD);
    const float4* __restrict__ p1 =
        (const float4*)(x + ((size_t)b * LP1 + (size_t)(i1 + 1)) * TT * DD);
    const float4* __restrict__ p2 =
        (const float4*)(x + ((size_t)b * LP1 + (size_t)(i2 + 1)) * TT * DD);

    float* __restrict__ sel = out + OFF_SEL;
    float4* __restrict__ o0 = (float4*)(sel + ((size_t)b * TOPK + 0) * TT * DD);
    float4* __restrict__ o1 = (float4*)(sel + ((size_t)b * TOPK + 1) * TT * DD);
    float4* __restrict__ o2 = (float4*)(sel + ((size_t)b * TOPK + 2) * TT * DD);

    const int TPS = TT / SPLIT3;   // 8 rows per block
    float4 mx = make_float4(-CUDART_INF_F, -CUDART_INF_F, -CUDART_INF_F, -CUDART_INF_F);

    #pragma unroll
    for (int tt = 0; tt < TPS; ++tt) {
        const size_t off = (size_t)(s * TPS + tt) * (DD / 4) + tid;
        float4 a = p0[off];
        float4 c = p1[off];
        float4 e = p2[off];
        // streaming stores: selected_layers is write-once, never re-read
        __stcs(&o0[off], a);
        __stcs(&o1[off], c);
        __stcs(&o2[off], e);
        float4 w;
        w.x = v0 * a.x + v1 * c.x + v2 * e.x;
        w.y = v0 * a.y + v1 * c.y + v2 * e.y;
        w.z = v0 * a.z + v1 * c.z + v2 * e.z;
        w.w = v0 * a.w + v1 * c.w + v2 * e.w;
        mx.x = fmaxf(mx.x, w.x);
        mx.y = fmaxf(mx.y, w.y);
        mx.z = fmaxf(mx.z, w.z);
        mx.w = fmaxf(mx.w, w.w);
    }

    float* gp = g_pooled + (size_t)b * DD + tid * 4;
    atomicMaxFloat(gp + 0, mx.x);
    atomicMaxFloat(gp + 1, mx.y);
    atomicMaxFloat(gp + 2, mx.z);
    atomicMaxFloat(gp + 3, mx.w);
}

// ---------------------------------------------------------------------------
// Kernel 4: grid = BB*FBLK blocks, 256 threads.
// Each block: load g_pooled[b] (4KB), redundant LN stats, normalize to smem,
// then a coalesced 32-output slice of the 1024->128 GEMV.
// ---------------------------------------------------------------------------
__global__ __launch_bounds__(256) void k_final(const float* __restrict__ gamma,
                                               const float* __restrict__ beta,
                                               const float* __restrict__ w_proj,
                                               const float* __restrict__ b_proj,
                                               float* __restrict__ out) {
    const int b   = blockIdx.x / FBLK;
    const int pb  = blockIdx.x % FBLK;    // which 32-output slice
    const int tid = threadIdx.x;
    const int lane = tid & 31, warp = tid >> 5;

    __shared__ float normed[DD];
    __shared__ float red[8], red2[8];
    __shared__ float s_stats[2];
    __shared__ float part[256];

    // load 1024 pooled values as float4 per thread
    float4 v = ((const float4*)(g_pooled + (size_t)b * DD))[tid];

    // LN stats
    {
        float s1 = v.x + v.y + v.z + v.w;
        float s2 = v.x * v.x + v.y * v.y + v.z * v.z + v.w * v.w;
        #pragma unroll
        for (int o = 16; o > 0; o >>= 1) {
            s1 += __shfl_down_sync(0xffffffffu, s1, o);
            s2 += __shfl_down_sync(0xffffffffu, s2, o);
        }
        if (lane == 0) { red[warp] = s1; red2[warp] = s2; }
    }
    __syncthreads();
    if (tid == 0) {
        float s1 = 0.f, s2 = 0.f;
        #pragma unroll
        for (int i = 0; i < 8; ++i) { s1 += red[i]; s2 += red2[i]; }
        float mu  = s1 * (1.0f / (float)DD);
        float var = s2 * (1.0f / (float)DD) - mu * mu;
        s_stats[0] = mu;
        s_stats[1] = rsqrtf(var + 1e-5f);
    }
    __syncthreads();

    // normalize into shared
    {
        const float mu = s_stats[0], rstd = s_stats[1];
        const float4 g4 = ((const float4*)gamma)[tid];
        const float4 be4 = ((const float4*)beta)[tid];
        float4 n;
        n.x = (v.x - mu) * rstd * g4.x + be4.x;
        n.y = (v.y - mu) * rstd * g4.y + be4.y;
        n.z = (v.z - mu) * rstd * g4.z + be4.z;
        n.w = (v.w - mu) * rstd * g4.w + be4.w;
        ((float4*)normed)[tid] = n;
    }
    __syncthreads();

    // GEMV slice: p = pb*32 + lane, d-chunk = warp (8 chunks of 128)
    {
        const int p  = pb * 32 + lane;
        const int d0 = warp * 128;
        float acc = 0.f;
        #pragma unroll 8
        for (int i = 0; i < 128; ++i)
            acc += normed[d0 + i] * w_proj[(size_t)(d0 + i) * PP + p];
        part[tid] = acc;
    }
    __syncthreads();
    if (tid < 32) {
        const int p = pb * 32 + tid;
        float acc = b_proj[p];
        #pragma unroll
        for (int c = 0; c < 8; ++c) acc += part[c * 32 + tid];
        out[OFF_PROJ + b * PP + p] = acc;
    }
}

// ---------------------------------------------------------------------------
// Launch
// ---------------------------------------------------------------------------
extern "C" void kernel_launch(void* const* d_in, const int* in_sizes, int n_in,
                              void* d_out, int out_size) {
    const float* x       = (const float*)d_in[0];  // wav2vec_ft (8,25,512,1024)
    const float* w_score = (const float*)d_in[1];  // (1024,1)
    const float* b_score = (const float*)d_in[2];  // (1,)
    const float* ln_g    = (const float*)d_in[3];  // (1024,)
    const float* ln_b    = (const float*)d_in[4];  // (1024,)
    const float* w_proj  = (const float*)d_in[5];  // (1024,128)
    const float* b_proj  = (const float*)d_in[6];  // (128,)
    float* out = (float*)d_out;

    k_scores<<<BB * LL * SPLIT1, 256>>>(x, w_score);
    k_topk<<<1, 256>>>(b_score, out);
    k_gather<<<BB * SPLIT3, 256>>>(x, out);
    k_final<<<BB * FBLK, 256>>>(ln_g, ln_b, w_proj, b_proj, out);
}